// round 12
// baseline (speedup 1.0000x reference)
#include <cuda_runtime.h>
#include <cuda_fp16.h>
#include <math.h>
#include <stdint.h>

// ---------------------------------------------------------------------------
// Problem constants
// ---------------------------------------------------------------------------
#define D_MODEL 1024
#define H_HEADS 16
#define HD      64
#define B_BATCH 2
#define S_SEQ   2048
#define M_ROWS  (B_BATCH * S_SEQ)      // 4096
#define QKV_N   (3 * D_MODEL)          // 3072
#define QKV_E   (B_BATCH * H_HEADS * S_SEQ * HD)   // 4,194,304 per q/k/v

// ---------------------------------------------------------------------------
// Scratch (device globals — allocation-free)
// ---------------------------------------------------------------------------
__device__ __align__(256) __half g_Ah  [M_ROWS * D_MODEL];  // fp16 activations
__device__ __align__(256) __half g_Bqkv[QKV_N  * D_MODEL];  // W_qkv^T fp16
__device__ __align__(256) __half g_Bout[D_MODEL * D_MODEL]; // W_out^T fp16
__device__ __align__(256) __half g_qkvh[3 * QKV_E];         // fp16 q|k|v [B,H,S,64]

// ---------------------------------------------------------------------------
// Helpers (portable PTX only: ldmatrix / mma.sync / cp.async)
// ---------------------------------------------------------------------------
__device__ __forceinline__ uint32_t smem_to_u32(const void* p) {
    uint32_t a;
    asm("{ .reg .u64 t; cvta.to.shared.u64 t, %1; cvt.u32.u64 %0, t; }"
        : "=r"(a) : "l"(p));
    return a;
}
__device__ __forceinline__ void cp_async16(uint32_t dst, const void* src) {
    asm volatile("cp.async.cg.shared.global [%0], [%1], 16;" :: "r"(dst), "l"(src));
}
__device__ __forceinline__ void cp_commit() { asm volatile("cp.async.commit_group;"); }
__device__ __forceinline__ void cp_wait1()  { asm volatile("cp.async.wait_group 1;"); }

__device__ __forceinline__ void ldsm_x4(uint32_t& r0, uint32_t& r1,
                                        uint32_t& r2, uint32_t& r3, uint32_t addr) {
    asm volatile("ldmatrix.sync.aligned.m8n8.x4.shared.b16 {%0,%1,%2,%3}, [%4];"
                 : "=r"(r0), "=r"(r1), "=r"(r2), "=r"(r3) : "r"(addr));
}
__device__ __forceinline__ void ldsm_x4_t(uint32_t& r0, uint32_t& r1,
                                          uint32_t& r2, uint32_t& r3, uint32_t addr) {
    asm volatile("ldmatrix.sync.aligned.m8n8.x4.trans.shared.b16 {%0,%1,%2,%3}, [%4];"
                 : "=r"(r0), "=r"(r1), "=r"(r2), "=r"(r3) : "r"(addr));
}
__device__ __forceinline__ void mma16816(float* c, const uint32_t* a, const uint32_t* b) {
    asm volatile("mma.sync.aligned.m16n8k16.row.col.f32.f16.f16.f32 "
                 "{%0,%1,%2,%3}, {%4,%5,%6,%7}, {%8,%9}, {%0,%1,%2,%3};"
                 : "+f"(c[0]), "+f"(c[1]), "+f"(c[2]), "+f"(c[3])
                 : "r"(a[0]), "r"(a[1]), "r"(a[2]), "r"(a[3]),
                   "r"(b[0]), "r"(b[1]));
}
__device__ __forceinline__ uint32_t packh2(float lo, float hi) {
    __half2 v = __floats2half2_rn(lo, hi);   // lo -> low 16 bits
    return *reinterpret_cast<uint32_t*>(&v);
}

// Swizzled byte offset of (row r, byte b within 128B row); XOR on 16B chunks.
#define SWZ(r, b) ((r) * 128 + ((b) ^ (((r) & 7) << 4)))

// ---------------------------------------------------------------------------
// Fused prep: x -> fp16 (blocks [0,4096)), W_qkv^T (blocks [4096,7168)),
// W_out^T (blocks [7168,8192)). 256 threads each.
// ---------------------------------------------------------------------------
#define PREP_XB   (M_ROWS * D_MODEL / (256 * 4))     // 4096
#define PREP_QB   ((QKV_N / 32) * (D_MODEL / 32))    // 3072
#define PREP_OB   ((D_MODEL / 32) * (D_MODEL / 32))  // 1024

__global__ void prep_kernel(const float* __restrict__ x,
                            const float* __restrict__ Wq,
                            const float* __restrict__ Wo,
                            __half* __restrict__ Ah,
                            __half* __restrict__ Bq,
                            __half* __restrict__ Bo)
{
    const int bid = blockIdx.x;
    const int tid = threadIdx.x;
    if (bid < PREP_XB) {
        const int idx = bid * 256 + tid;
        float4 v = *(const float4*)(x + (size_t)idx * 4);
        *(__half2*)(Ah + (size_t)idx * 4)     = __floats2half2_rn(v.x, v.y);
        *(__half2*)(Ah + (size_t)idx * 4 + 2) = __floats2half2_rn(v.z, v.w);
        return;
    }
    __shared__ float tile[32][33];
    const float* W; __half* out; int N, rel;
    if (bid < PREP_XB + PREP_QB) { rel = bid - PREP_XB; W = Wq; out = Bq; N = QKV_N; }
    else                         { rel = bid - PREP_XB - PREP_QB; W = Wo; out = Bo; N = D_MODEL; }
    const int nblk = N / 32;
    const int n0 = (rel % nblk) * 32, k0 = (rel / nblk) * 32;
    const int tx = tid & 31, ty = tid >> 5;   // (32, 8)
    #pragma unroll
    for (int i = 0; i < 4; ++i)
        tile[ty + i * 8][tx] = W[(size_t)(k0 + ty + i * 8) * N + n0 + tx];
    __syncthreads();
    #pragma unroll
    for (int i = 0; i < 4; ++i) {
        const int n = n0 + ty + i * 8;
        const int k = k0 + tx;
        out[(size_t)n * D_MODEL + k] = __float2half_rn(tile[tx][ty + i * 8]);
    }
}

// ---------------------------------------------------------------------------
// Tensor-core GEMM via mma.sync (HMMA fp16), CTA 128x128, BK=64, K=1024.
// 3-stage cp.async pipeline, one __syncthreads per chunk.
// MODE 0: fp32 C out.  MODE 1: qkv epilogue -> fp16 [3][B,H,S,64], q scaled.
// ---------------------------------------------------------------------------
#define BM 128
#define BN 128
#define BK 64
#define NCHUNK (D_MODEL / BK)                 // 16
#define STAGE_BYTES (BM * 128 + BN * 128)     // 32768
#define NSTAGE 3
#define GEMM_SMEM (NSTAGE * STAGE_BYTES)      // 98304

template <int MODE>
__global__ __launch_bounds__(256, 2)
void gemm_h_mma(const __half* __restrict__ A,
                const __half* __restrict__ B,
                const float* __restrict__ bias,
                float* __restrict__ C,
                __half* __restrict__ qkvh,
                int N)
{
    extern __shared__ char smem[];
    const uint32_t sb = smem_to_u32(smem);
    const int tid  = threadIdx.x;
    const int wid  = tid >> 5, lane = tid & 31;
    const int wm   = wid & 3;
    const int wn   = wid >> 2;
    const int m0   = blockIdx.y * BM;
    const int n0   = blockIdx.x * BN;

    const __half* Ab = A + (size_t)m0 * D_MODEL;
    const __half* Bb = B + (size_t)n0 * D_MODEL;

    auto load_stage = [&](int kc, int s) {
        const uint32_t ab = sb + s * STAGE_BYTES;
        const uint32_t bb = ab + BM * 128;
        const int koff = kc * BK;
        #pragma unroll
        for (int p = 0; p < 4; ++p) {
            const int idx = tid + p * 256;
            const int r = idx >> 3, q = idx & 7;
            cp_async16(ab + r * 128 + ((q ^ (r & 7)) << 4),
                       Ab + (size_t)r * D_MODEL + koff + q * 8);
        }
        #pragma unroll
        for (int p = 0; p < 4; ++p) {
            const int idx = tid + p * 256;
            const int r = idx >> 3, q = idx & 7;
            cp_async16(bb + r * 128 + ((q ^ (r & 7)) << 4),
                       Bb + (size_t)r * D_MODEL + koff + q * 8);
        }
    };

    float acc[2][8][4];
    #pragma unroll
    for (int mt = 0; mt < 2; ++mt)
        #pragma unroll
        for (int nt = 0; nt < 8; ++nt)
            #pragma unroll
            for (int i = 0; i < 4; ++i) acc[mt][nt][i] = 0.0f;

    load_stage(0, 0); cp_commit();
    load_stage(1, 1); cp_commit();

    int s = 0, ls = 2;                       // consume stage, load stage
    for (int kc = 0; kc < NCHUNK; ++kc) {
        cp_wait1();
        __syncthreads();                     // stage s ready; stage ls reads done

        const uint32_t ab = sb + s * STAGE_BYTES;
        const uint32_t bb = ab + BM * 128;

        #pragma unroll
        for (int ks = 0; ks < 4; ++ks) {
            const int kb = ks * 32;

            uint32_t av[2][4];
            #pragma unroll
            for (int mt = 0; mt < 2; ++mt) {
                const int r  = wm * 32 + mt * 16 + (lane & 15);
                const int cb = kb + ((lane >> 4) << 4);
                ldsm_x4(av[mt][0], av[mt][1], av[mt][2], av[mt][3],
                        ab + SWZ(r, cb));
            }
            uint32_t bv[8][2];
            #pragma unroll
            for (int nt2 = 0; nt2 < 4; ++nt2) {
                const int r  = wn * 64 + nt2 * 16 + (lane & 7) + ((lane >> 4) << 3);
                const int cb = kb + (((lane >> 3) & 1) << 4);
                uint32_t t0, t1, t2, t3;
                ldsm_x4(t0, t1, t2, t3, bb + SWZ(r, cb));
                bv[nt2 * 2][0] = t0;  bv[nt2 * 2][1] = t1;
                bv[nt2 * 2 + 1][0] = t2;  bv[nt2 * 2 + 1][1] = t3;
            }
            #pragma unroll
            for (int mt = 0; mt < 2; ++mt)
                #pragma unroll
                for (int nt = 0; nt < 8; ++nt)
                    mma16816(acc[mt][nt], av[mt], bv[nt]);
        }

        if (kc + 2 < NCHUNK) load_stage(kc + 2, ls);
        cp_commit();
        s  = (s  == NSTAGE - 1) ? 0 : s + 1;
        ls = (ls == NSTAGE - 1) ? 0 : ls + 1;
    }

    const int g  = lane >> 2;
    const int tg = lane & 3;
    #pragma unroll
    for (int mt = 0; mt < 2; ++mt) {
        const int row0 = m0 + wm * 32 + mt * 16 + g;
        #pragma unroll
        for (int nt = 0; nt < 8; ++nt) {
            const int col = n0 + wn * 64 + nt * 8 + tg * 2;
            const float2 bv = *(const float2*)(bias + col);
            float v0x = acc[mt][nt][0] + bv.x, v0y = acc[mt][nt][1] + bv.y;
            float v1x = acc[mt][nt][2] + bv.x, v1y = acc[mt][nt][3] + bv.y;
            if (MODE == 0) {
                *(float2*)(C + (size_t)row0 * N + col)       = make_float2(v0x, v0y);
                *(float2*)(C + (size_t)(row0 + 8) * N + col) = make_float2(v1x, v1y);
            } else {
                const int sec = col >> 10;
                const int hh  = (col >> 6) & 15;
                const int dd  = col & 63;
                const float sc = (sec == 0) ? 0.125f : 1.0f;   // fold 1/sqrt(64) into q
                __half* dst = qkvh + (size_t)sec * QKV_E;
                const size_t i0 = ((size_t)((row0 >> 11) * H_HEADS + hh) * S_SEQ
                                   + (row0 & 2047)) * HD + dd;
                const size_t i1 = ((size_t)(((row0 + 8) >> 11) * H_HEADS + hh) * S_SEQ
                                   + ((row0 + 8) & 2047)) * HD + dd;
                *(uint32_t*)(dst + i0) = packh2(v0x * sc, v0y * sc);
                *(uint32_t*)(dst + i1) = packh2(v1x * sc, v1y * sc);
            }
        }
    }
}

// ---------------------------------------------------------------------------
// Flash attention on tensor cores (mma.sync fp16, fp32 accum).
// 256 threads (8 warps), 128 q-rows/CTA, Bc=64.
// DEFERRED-PV pipeline: at iter t, PV(t-1) HMMAs interleave with exp(t)
// MUFUs (independent), overlapping the tensor and MUFU pipes within a warp.
// oacc op sequence (...PV(t-1), rescale alpha(t), PV(t)...) is unchanged
// -> bit-identical numerics. K ring: 3 stages; V ring: 4 stages (V(t-1)
// must survive one extra iteration).
// ---------------------------------------------------------------------------
#define AQ 128
#define AK 64
#define AIT (S_SEQ / AK)          // 32
// dynamic smem: Q 16KB | K[3] 8KB | V[4] 8KB = 72 KB
#define SM_Q 0
#define SM_K 16384
#define SM_V (16384 + 3 * 8192)
#define ATT_SMEM (SM_V + 4 * 8192)   // 73728

__global__ __launch_bounds__(256)
void flash_attn_h(const __half* __restrict__ qkvh,
                  __half* __restrict__ Aout)
{
    extern __shared__ char sm[];
    const uint32_t sb = smem_to_u32(sm);
    const int tid = threadIdx.x, w = tid >> 5, lane = tid & 31;
    const int qt = blockIdx.x, h = blockIdx.y, b = blockIdx.z;

    const __half* qb = qkvh + ((size_t)(b * H_HEADS + h) * S_SEQ) * HD;
    const __half* kb = qb + QKV_E;
    const __half* vb = qb + 2 * (size_t)QKV_E;

    // K -> stage t%3, V -> stage t&3
    auto load_kv = [&](int t) {
        const __half* ksrc = kb + (size_t)t * AK * HD;
        const __half* vsrc = vb + (size_t)t * AK * HD;
        const uint32_t kdst = sb + SM_K + (t % 3) * 8192;
        const uint32_t vdst = sb + SM_V + (t & 3) * 8192;
        #pragma unroll
        for (int p = 0; p < 2; ++p) {
            const int idx = tid + p * 256;
            const int r = idx >> 3, q = idx & 7;
            const uint32_t off = r * 128 + ((q ^ (r & 7)) << 4);
            cp_async16(kdst + off, ksrc + (size_t)r * HD + q * 8);
            cp_async16(vdst + off, vsrc + (size_t)r * HD + q * 8);
        }
    };

    // group0: Q + KV0 ; group1: KV1
    #pragma unroll
    for (int p = 0; p < 4; ++p) {
        const int idx = tid + p * 256;
        const int r = idx >> 3, q = idx & 7;
        cp_async16(sb + SM_Q + r * 128 + ((q ^ (r & 7)) << 4),
                   qb + (size_t)(qt * AQ + r) * HD + q * 8);
    }
    load_kv(0); cp_commit();
    load_kv(1); cp_commit();
    cp_wait1();
    __syncthreads();

    // Q fragments (persist): warp w's 16 rows
    uint32_t qf[4][4];
    #pragma unroll
    for (int ks = 0; ks < 4; ++ks) {
        const int r  = w * 16 + (lane & 15);
        const int cb = ks * 32 + ((lane >> 4) << 4);
        ldsm_x4(qf[ks][0], qf[ks][1], qf[ks][2], qf[ks][3], sb + SM_Q + SWZ(r, cb));
    }

    float m2[2] = {-1e30f, -1e30f}, l2[2] = {0.0f, 0.0f};
    float oacc[8][4];
    #pragma unroll
    for (int nt = 0; nt < 8; ++nt)
        #pragma unroll
        for (int i = 0; i < 4; ++i) oacc[nt][i] = 0.0f;

    uint32_t pfprev[4][4];

    for (int t = 0; t < AIT; ++t) {
        cp_wait1();
        __syncthreads();   // K(t),V(t) ready; stale K/V stages free to refill

        // ---- S = Q K^T from K stage t%3 ----
        float sacc[8][4];
        #pragma unroll
        for (int nt = 0; nt < 8; ++nt)
            #pragma unroll
            for (int i = 0; i < 4; ++i) sacc[nt][i] = 0.0f;

        const uint32_t kbuf = sb + SM_K + (t % 3) * 8192;
        #pragma unroll
        for (int ks = 0; ks < 4; ++ks) {
            uint32_t bv[8][2];
            #pragma unroll
            for (int nt2 = 0; nt2 < 4; ++nt2) {
                const int r  = nt2 * 16 + (lane & 7) + ((lane >> 4) << 3);
                const int cb = ks * 32 + (((lane >> 3) & 1) << 4);
                uint32_t t0, t1, t2, t3;
                ldsm_x4(t0, t1, t2, t3, kbuf + SWZ(r, cb));
                bv[nt2 * 2][0] = t0;  bv[nt2 * 2][1] = t1;
                bv[nt2 * 2 + 1][0] = t2;  bv[nt2 * 2 + 1][1] = t3;
            }
            #pragma unroll
            for (int nt = 0; nt < 8; ++nt)
                mma16816(sacc[nt], qf[ks], bv[nt]);
        }

        // ---- row stats (max, alpha) ----
        float alpha[2];
        #pragma unroll
        for (int hf = 0; hf < 2; ++hf) {
            float tmax = -1e30f;
            #pragma unroll
            for (int nt = 0; nt < 8; ++nt)
                tmax = fmaxf(tmax, fmaxf(sacc[nt][2 * hf], sacc[nt][2 * hf + 1]));
            tmax = fmaxf(tmax, __shfl_xor_sync(0xffffffffu, tmax, 1));
            tmax = fmaxf(tmax, __shfl_xor_sync(0xffffffffu, tmax, 2));
            const float mn = fmaxf(m2[hf], tmax);
            alpha[hf] = __expf(m2[hf] - mn);
            m2[hf] = mn;
        }

        // ---- interleaved: PV(t-1) HMMAs + exp(t) MUFUs ----
        uint32_t pfnew[4][4];
        float rs0 = 0.0f, rs1 = 0.0f;
        const uint32_t vbuf = sb + SM_V + ((t - 1) & 3) * 8192;
        #pragma unroll
        for (int c = 0; c < 4; ++c) {
            if (t > 0) {
                uint32_t vv[8][2];
                #pragma unroll
                for (int ng = 0; ng < 4; ++ng) {
                    const int r  = c * 16 + (lane & 15);
                    const int cb = ng * 32 + ((lane >> 4) << 4);
                    uint32_t t0, t1, t2, t3;
                    ldsm_x4_t(t0, t1, t2, t3, vbuf + SWZ(r, cb));
                    vv[ng * 2][0] = t0;  vv[ng * 2][1] = t1;
                    vv[ng * 2 + 1][0] = t2;  vv[ng * 2 + 1][1] = t3;
                }
                #pragma unroll
                for (int nt = 0; nt < 8; ++nt)
                    mma16816(oacc[nt], pfprev[c], vv[nt]);
            }
            // exp(t) for chunk c (independent of the PV above)
            const float pa0 = __expf(sacc[2 * c][0]     - m2[0]);
            const float pa1 = __expf(sacc[2 * c][1]     - m2[0]);
            const float pa2 = __expf(sacc[2 * c][2]     - m2[1]);
            const float pa3 = __expf(sacc[2 * c][3]     - m2[1]);
            const float pb0 = __expf(sacc[2 * c + 1][0] - m2[0]);
            const float pb1 = __expf(sacc[2 * c + 1][1] - m2[0]);
            const float pb2 = __expf(sacc[2 * c + 1][2] - m2[1]);
            const float pb3 = __expf(sacc[2 * c + 1][3] - m2[1]);
            rs0 += pa0 + pa1 + pb0 + pb1;
            rs1 += pa2 + pa3 + pb2 + pb3;
            pfnew[c][0] = packh2(pa0, pa1);
            pfnew[c][1] = packh2(pa2, pa3);
            pfnew[c][2] = packh2(pb0, pb1);
            pfnew[c][3] = packh2(pb2, pb3);
        }

        // ---- rescale oacc by alpha(t) (AFTER PV(t-1)), update l ----
        #pragma unroll
        for (int nt = 0; nt < 8; ++nt) {
            oacc[nt][0] *= alpha[0];  oacc[nt][1] *= alpha[0];
            oacc[nt][2] *= alpha[1];  oacc[nt][3] *= alpha[1];
        }
        rs0 += __shfl_xor_sync(0xffffffffu, rs0, 1);
        rs0 += __shfl_xor_sync(0xffffffffu, rs0, 2);
        rs1 += __shfl_xor_sync(0xffffffffu, rs1, 1);
        rs1 += __shfl_xor_sync(0xffffffffu, rs1, 2);
        l2[0] = l2[0] * alpha[0] + rs0;
        l2[1] = l2[1] * alpha[1] + rs1;

        #pragma unroll
        for (int c = 0; c < 4; ++c)
            #pragma unroll
            for (int j = 0; j < 4; ++j) pfprev[c][j] = pfnew[c][j];

        if (t + 2 < AIT) load_kv(t + 2);
        cp_commit();
    }

    // ---- final PV(AIT-1) ----
    {
        const uint32_t vbuf = sb + SM_V + ((AIT - 1) & 3) * 8192;
        #pragma unroll
        for (int c = 0; c < 4; ++c) {
            uint32_t vv[8][2];
            #pragma unroll
            for (int ng = 0; ng < 4; ++ng) {
                const int r  = c * 16 + (lane & 15);
                const int cb = ng * 32 + ((lane >> 4) << 4);
                uint32_t t0, t1, t2, t3;
                ldsm_x4_t(t0, t1, t2, t3, vbuf + SWZ(r, cb));
                vv[ng * 2][0] = t0;  vv[ng * 2][1] = t1;
                vv[ng * 2 + 1][0] = t2;  vv[ng * 2 + 1][1] = t3;
            }
            #pragma unroll
            for (int nt = 0; nt < 8; ++nt)
                mma16816(oacc[nt], pfprev[c], vv[nt]);
        }
    }

    // ---- epilogue: normalize, write fp16 A rows [M,1024] at col h*64+d ----
    const int g  = lane >> 2;
    const int tg = lane & 3;
    const float inv0 = __fdividef(1.0f, l2[0]);
    const float inv1 = __fdividef(1.0f, l2[1]);
    const int row0 = b * S_SEQ + qt * AQ + w * 16 + g;
    #pragma unroll
    for (int nt = 0; nt < 8; ++nt) {
        const int col = h * HD + nt * 8 + tg * 2;
        *(uint32_t*)(Aout + (size_t)row0 * D_MODEL + col) =
            packh2(oacc[nt][0] * inv0, oacc[nt][1] * inv0);
        *(uint32_t*)(Aout + (size_t)(row0 + 8) * D_MODEL + col) =
            packh2(oacc[nt][2] * inv1, oacc[nt][3] * inv1);
    }
}

// ---------------------------------------------------------------------------
// Launch
// ---------------------------------------------------------------------------
extern "C" void kernel_launch(void* const* d_in, const int* in_sizes, int n_in,
                              void* d_out, int out_size)
{
    const float* x     = (const float*)d_in[0];
    const float* W_qkv = (const float*)d_in[1];
    const float* b_qkv = (const float*)d_in[2];
    const float* W_out = (const float*)d_in[3];
    const float* b_out = (const float*)d_in[4];
    float* out = (float*)d_out;

    __half *Ah, *Bqkv, *Bout, *qkvh;
    cudaGetSymbolAddress((void**)&Ah,   g_Ah);
    cudaGetSymbolAddress((void**)&Bqkv, g_Bqkv);
    cudaGetSymbolAddress((void**)&Bout, g_Bout);
    cudaGetSymbolAddress((void**)&qkvh, g_qkvh);

    cudaFuncSetAttribute(gemm_h_mma<0>,
                         cudaFuncAttributeMaxDynamicSharedMemorySize, GEMM_SMEM);
    cudaFuncSetAttribute(gemm_h_mma<1>,
                         cudaFuncAttributeMaxDynamicSharedMemorySize, GEMM_SMEM);
    cudaFuncSetAttribute(flash_attn_h,
                         cudaFuncAttributeMaxDynamicSharedMemorySize, ATT_SMEM);

    // 1) fused prep: x -> fp16, both weights -> transposed fp16
    prep_kernel<<<PREP_XB + PREP_QB + PREP_OB, 256>>>(x, W_qkv, W_out, Ah, Bqkv, Bout);

    // 2) QKV projection (HMMA fp16) -> fp16 q|k|v [B,H,S,64], q pre-scaled
    gemm_h_mma<1><<<dim3(QKV_N / BN, M_ROWS / BM), 256, GEMM_SMEM>>>(
        Ah, Bqkv, b_qkv, nullptr, qkvh, QKV_N);

    // 3) Flash attention (HMMA fp16, deferred-PV overlap) -> fp16 A
    flash_attn_h<<<dim3(S_SEQ / AQ, H_HEADS, B_BATCH), 256, ATT_SMEM>>>(qkvh, Ah);

    // 4) Output projection (HMMA fp16) -> out
    gemm_h_mma<0><<<dim3(D_MODEL / BN, M_ROWS / BM), 256, GEMM_SMEM>>>(
        Ah, Bout, b_out, out, nullptr, D_MODEL);
}

// round 16
// speedup vs baseline: 1.1833x; 1.1833x over previous
#include <cuda_runtime.h>
#include <cuda_fp16.h>
#include <math.h>
#include <stdint.h>

// ---------------------------------------------------------------------------
// Problem constants
// ---------------------------------------------------------------------------
#define D_MODEL 1024
#define H_HEADS 16
#define HD      64
#define B_BATCH 2
#define S_SEQ   2048
#define M_ROWS  (B_BATCH * S_SEQ)      // 4096
#define QKV_N   (3 * D_MODEL)          // 3072
#define QKV_E   (B_BATCH * H_HEADS * S_SEQ * HD)   // 4,194,304 per q/k/v

// q pre-scale: 1/sqrt(64) * log2(e)  (softmax done in base-2)
#define Q_SCALE 0.1803368801111204f

// ---------------------------------------------------------------------------
// Scratch (device globals — allocation-free)
// ---------------------------------------------------------------------------
__device__ __align__(256) __half g_Ah  [M_ROWS * D_MODEL];  // fp16 activations
__device__ __align__(256) __half g_Bqkv[QKV_N  * D_MODEL];  // W_qkv^T fp16
__device__ __align__(256) __half g_Bout[D_MODEL * D_MODEL]; // W_out^T fp16
__device__ __align__(256) __half g_qkvh[3 * QKV_E];         // fp16 q|k|v [B,H,S,64]

// ---------------------------------------------------------------------------
// Helpers (portable PTX only: ldmatrix / mma.sync / cp.async)
// ---------------------------------------------------------------------------
__device__ __forceinline__ uint32_t smem_to_u32(const void* p) {
    uint32_t a;
    asm("{ .reg .u64 t; cvta.to.shared.u64 t, %1; cvt.u32.u64 %0, t; }"
        : "=r"(a) : "l"(p));
    return a;
}
__device__ __forceinline__ void cp_async16(uint32_t dst, const void* src) {
    asm volatile("cp.async.cg.shared.global [%0], [%1], 16;" :: "r"(dst), "l"(src));
}
__device__ __forceinline__ void cp_commit() { asm volatile("cp.async.commit_group;"); }
__device__ __forceinline__ void cp_wait1()  { asm volatile("cp.async.wait_group 1;"); }

__device__ __forceinline__ void ldsm_x4(uint32_t& r0, uint32_t& r1,
                                        uint32_t& r2, uint32_t& r3, uint32_t addr) {
    asm volatile("ldmatrix.sync.aligned.m8n8.x4.shared.b16 {%0,%1,%2,%3}, [%4];"
                 : "=r"(r0), "=r"(r1), "=r"(r2), "=r"(r3) : "r"(addr));
}
__device__ __forceinline__ void ldsm_x4_t(uint32_t& r0, uint32_t& r1,
                                          uint32_t& r2, uint32_t& r3, uint32_t addr) {
    asm volatile("ldmatrix.sync.aligned.m8n8.x4.trans.shared.b16 {%0,%1,%2,%3}, [%4];"
                 : "=r"(r0), "=r"(r1), "=r"(r2), "=r"(r3) : "r"(addr));
}
__device__ __forceinline__ void mma16816(float* c, const uint32_t* a, const uint32_t* b) {
    asm volatile("mma.sync.aligned.m16n8k16.row.col.f32.f16.f16.f32 "
                 "{%0,%1,%2,%3}, {%4,%5,%6,%7}, {%8,%9}, {%0,%1,%2,%3};"
                 : "+f"(c[0]), "+f"(c[1]), "+f"(c[2]), "+f"(c[3])
                 : "r"(a[0]), "r"(a[1]), "r"(a[2]), "r"(a[3]),
                   "r"(b[0]), "r"(b[1]));
}
__device__ __forceinline__ uint32_t packh2(float lo, float hi) {
    __half2 v = __floats2half2_rn(lo, hi);   // lo -> low 16 bits
    return *reinterpret_cast<uint32_t*>(&v);
}

// Swizzled byte offset of (row r, byte b within 128B row); XOR on 16B chunks.
#define SWZ(r, b) ((r) * 128 + ((b) ^ (((r) & 7) << 4)))

// ---------------------------------------------------------------------------
// Fused prep: x -> fp16 (blocks [0,4096)), W_qkv^T (blocks [4096,7168)),
// W_out^T (blocks [7168,8192)). 256 threads each.
// ---------------------------------------------------------------------------
#define PREP_XB   (M_ROWS * D_MODEL / (256 * 4))     // 4096
#define PREP_QB   ((QKV_N / 32) * (D_MODEL / 32))    // 3072
#define PREP_OB   ((D_MODEL / 32) * (D_MODEL / 32))  // 1024

__global__ void prep_kernel(const float* __restrict__ x,
                            const float* __restrict__ Wq,
                            const float* __restrict__ Wo,
                            __half* __restrict__ Ah,
                            __half* __restrict__ Bq,
                            __half* __restrict__ Bo)
{
    const int bid = blockIdx.x;
    const int tid = threadIdx.x;
    if (bid < PREP_XB) {
        const int idx = bid * 256 + tid;
        float4 v = *(const float4*)(x + (size_t)idx * 4);
        *(__half2*)(Ah + (size_t)idx * 4)     = __floats2half2_rn(v.x, v.y);
        *(__half2*)(Ah + (size_t)idx * 4 + 2) = __floats2half2_rn(v.z, v.w);
        return;
    }
    __shared__ float tile[32][33];
    const float* W; __half* out; int N, rel;
    if (bid < PREP_XB + PREP_QB) { rel = bid - PREP_XB; W = Wq; out = Bq; N = QKV_N; }
    else                         { rel = bid - PREP_XB - PREP_QB; W = Wo; out = Bo; N = D_MODEL; }
    const int nblk = N / 32;
    const int n0 = (rel % nblk) * 32, k0 = (rel / nblk) * 32;
    const int tx = tid & 31, ty = tid >> 5;   // (32, 8)
    #pragma unroll
    for (int i = 0; i < 4; ++i)
        tile[ty + i * 8][tx] = W[(size_t)(k0 + ty + i * 8) * N + n0 + tx];
    __syncthreads();
    #pragma unroll
    for (int i = 0; i < 4; ++i) {
        const int n = n0 + ty + i * 8;
        const int k = k0 + tx;
        out[(size_t)n * D_MODEL + k] = __float2half_rn(tile[tx][ty + i * 8]);
    }
}

// ---------------------------------------------------------------------------
// Tensor-core GEMM via mma.sync (HMMA fp16), CTA 128x128, BK=64, K=1024.
// 3-stage cp.async pipeline, one __syncthreads per chunk.
// MODE 0: fp32 C out.  MODE 1: qkv epilogue -> fp16 [3][B,H,S,64],
//         q pre-scaled by 1/sqrt(HD)*log2(e) (softmax in base-2).
// ---------------------------------------------------------------------------
#define BM 128
#define BN 128
#define BK 64
#define NCHUNK (D_MODEL / BK)                 // 16
#define STAGE_BYTES (BM * 128 + BN * 128)     // 32768
#define NSTAGE 3
#define GEMM_SMEM (NSTAGE * STAGE_BYTES)      // 98304

template <int MODE>
__global__ __launch_bounds__(256, 2)
void gemm_h_mma(const __half* __restrict__ A,
                const __half* __restrict__ B,
                const float* __restrict__ bias,
                float* __restrict__ C,
                __half* __restrict__ qkvh,
                int N)
{
    extern __shared__ char smem[];
    const uint32_t sb = smem_to_u32(smem);
    const int tid  = threadIdx.x;
    const int wid  = tid >> 5, lane = tid & 31;
    const int wm   = wid & 3;
    const int wn   = wid >> 2;
    const int m0   = blockIdx.y * BM;
    const int n0   = blockIdx.x * BN;

    const __half* Ab = A + (size_t)m0 * D_MODEL;
    const __half* Bb = B + (size_t)n0 * D_MODEL;

    auto load_stage = [&](int kc, int s) {
        const uint32_t ab = sb + s * STAGE_BYTES;
        const uint32_t bb = ab + BM * 128;
        const int koff = kc * BK;
        #pragma unroll
        for (int p = 0; p < 4; ++p) {
            const int idx = tid + p * 256;
            const int r = idx >> 3, q = idx & 7;
            cp_async16(ab + r * 128 + ((q ^ (r & 7)) << 4),
                       Ab + (size_t)r * D_MODEL + koff + q * 8);
        }
        #pragma unroll
        for (int p = 0; p < 4; ++p) {
            const int idx = tid + p * 256;
            const int r = idx >> 3, q = idx & 7;
            cp_async16(bb + r * 128 + ((q ^ (r & 7)) << 4),
                       Bb + (size_t)r * D_MODEL + koff + q * 8);
        }
    };

    float acc[2][8][4];
    #pragma unroll
    for (int mt = 0; mt < 2; ++mt)
        #pragma unroll
        for (int nt = 0; nt < 8; ++nt)
            #pragma unroll
            for (int i = 0; i < 4; ++i) acc[mt][nt][i] = 0.0f;

    load_stage(0, 0); cp_commit();
    load_stage(1, 1); cp_commit();

    int s = 0, ls = 2;                       // consume stage, load stage
    for (int kc = 0; kc < NCHUNK; ++kc) {
        cp_wait1();
        __syncthreads();                     // stage s ready; stage ls reads done

        const uint32_t ab = sb + s * STAGE_BYTES;
        const uint32_t bb = ab + BM * 128;

        #pragma unroll
        for (int ks = 0; ks < 4; ++ks) {
            const int kb = ks * 32;

            uint32_t av[2][4];
            #pragma unroll
            for (int mt = 0; mt < 2; ++mt) {
                const int r  = wm * 32 + mt * 16 + (lane & 15);
                const int cb = kb + ((lane >> 4) << 4);
                ldsm_x4(av[mt][0], av[mt][1], av[mt][2], av[mt][3],
                        ab + SWZ(r, cb));
            }
            uint32_t bv[8][2];
            #pragma unroll
            for (int nt2 = 0; nt2 < 4; ++nt2) {
                const int r  = wn * 64 + nt2 * 16 + (lane & 7) + ((lane >> 4) << 3);
                const int cb = kb + (((lane >> 3) & 1) << 4);
                uint32_t t0, t1, t2, t3;
                ldsm_x4(t0, t1, t2, t3, bb + SWZ(r, cb));
                bv[nt2 * 2][0] = t0;  bv[nt2 * 2][1] = t1;
                bv[nt2 * 2 + 1][0] = t2;  bv[nt2 * 2 + 1][1] = t3;
            }
            #pragma unroll
            for (int mt = 0; mt < 2; ++mt)
                #pragma unroll
                for (int nt = 0; nt < 8; ++nt)
                    mma16816(acc[mt][nt], av[mt], bv[nt]);
        }

        if (kc + 2 < NCHUNK) load_stage(kc + 2, ls);
        cp_commit();
        s  = (s  == NSTAGE - 1) ? 0 : s + 1;
        ls = (ls == NSTAGE - 1) ? 0 : ls + 1;
    }

    const int g  = lane >> 2;
    const int tg = lane & 3;
    #pragma unroll
    for (int mt = 0; mt < 2; ++mt) {
        const int row0 = m0 + wm * 32 + mt * 16 + g;
        #pragma unroll
        for (int nt = 0; nt < 8; ++nt) {
            const int col = n0 + wn * 64 + nt * 8 + tg * 2;
            const float2 bv = *(const float2*)(bias + col);
            float v0x = acc[mt][nt][0] + bv.x, v0y = acc[mt][nt][1] + bv.y;
            float v1x = acc[mt][nt][2] + bv.x, v1y = acc[mt][nt][3] + bv.y;
            if (MODE == 0) {
                *(float2*)(C + (size_t)row0 * N + col)       = make_float2(v0x, v0y);
                *(float2*)(C + (size_t)(row0 + 8) * N + col) = make_float2(v1x, v1y);
            } else {
                const int sec = col >> 10;
                const int hh  = (col >> 6) & 15;
                const int dd  = col & 63;
                const float sc = (sec == 0) ? Q_SCALE : 1.0f;
                __half* dst = qkvh + (size_t)sec * QKV_E;
                const size_t i0 = ((size_t)((row0 >> 11) * H_HEADS + hh) * S_SEQ
                                   + (row0 & 2047)) * HD + dd;
                const size_t i1 = ((size_t)(((row0 + 8) >> 11) * H_HEADS + hh) * S_SEQ
                                   + ((row0 + 8) & 2047)) * HD + dd;
                *(uint32_t*)(dst + i0) = packh2(v0x * sc, v0y * sc);
                *(uint32_t*)(dst + i1) = packh2(v1x * sc, v1y * sc);
            }
        }
    }
}

// ---------------------------------------------------------------------------
// Flash attention on tensor cores (mma.sync fp16, fp32 accum).
// R11 structure (proven fastest): 256 threads (8 warps), 128 q-rows/CTA,
// Bc=64; 3-stage cp.async K/V rings, one sync per tile. Softmax in base-2
// (q pre-scaled by log2(e)/sqrt(HD) -> exp2f everywhere).
// ---------------------------------------------------------------------------
#define AQ 128
#define AK 64
#define AIT (S_SEQ / AK)          // 32
// dynamic smem: Q 16KB | K[3] 8KB each | V[3] 8KB each = 64 KB
#define SM_Q 0
#define SM_K 16384
#define SM_V (16384 + 3 * 8192)
#define ATT_SMEM (SM_V + 3 * 8192)   // 65536

__global__ __launch_bounds__(256)
void flash_attn_h(const __half* __restrict__ qkvh,
                  __half* __restrict__ Aout)
{
    extern __shared__ char sm[];
    const uint32_t sb = smem_to_u32(sm);
    const int tid = threadIdx.x, w = tid >> 5, lane = tid & 31;
    const int qt = blockIdx.x, h = blockIdx.y, b = blockIdx.z;

    const __half* qb = qkvh + ((size_t)(b * H_HEADS + h) * S_SEQ) * HD;
    const __half* kb = qb + QKV_E;
    const __half* vb = qb + 2 * (size_t)QKV_E;

    auto load_kv = [&](int t, int s) {
        const __half* ksrc = kb + (size_t)t * AK * HD;
        const __half* vsrc = vb + (size_t)t * AK * HD;
        #pragma unroll
        for (int p = 0; p < 2; ++p) {
            const int idx = tid + p * 256;
            const int r = idx >> 3, q = idx & 7;
            const uint32_t off = r * 128 + ((q ^ (r & 7)) << 4);
            cp_async16(sb + SM_K + s * 8192 + off, ksrc + (size_t)r * HD + q * 8);
            cp_async16(sb + SM_V + s * 8192 + off, vsrc + (size_t)r * HD + q * 8);
        }
    };

    // group0: Q + KV0 ; group1: KV1
    #pragma unroll
    for (int p = 0; p < 4; ++p) {
        const int idx = tid + p * 256;
        const int r = idx >> 3, q = idx & 7;
        cp_async16(sb + SM_Q + r * 128 + ((q ^ (r & 7)) << 4),
                   qb + (size_t)(qt * AQ + r) * HD + q * 8);
    }
    load_kv(0, 0); cp_commit();
    load_kv(1, 1); cp_commit();
    cp_wait1();
    __syncthreads();

    // Q fragments (persist): warp w's 16 rows
    uint32_t qf[4][4];
    #pragma unroll
    for (int ks = 0; ks < 4; ++ks) {
        const int r  = w * 16 + (lane & 15);
        const int cb = ks * 32 + ((lane >> 4) << 4);
        ldsm_x4(qf[ks][0], qf[ks][1], qf[ks][2], qf[ks][3], sb + SM_Q + SWZ(r, cb));
    }

    float m2[2] = {-1e30f, -1e30f}, l2[2] = {0.0f, 0.0f};
    float oacc[8][4];
    #pragma unroll
    for (int nt = 0; nt < 8; ++nt)
        #pragma unroll
        for (int i = 0; i < 4; ++i) oacc[nt][i] = 0.0f;

    int s = 0, ls = 2;
    for (int t = 0; t < AIT; ++t) {
        if (t > 0) { cp_wait1(); __syncthreads(); }

        // ---- S = Q K^T (scores already in log2 domain) ----
        float sacc[8][4];
        #pragma unroll
        for (int nt = 0; nt < 8; ++nt)
            #pragma unroll
            for (int i = 0; i < 4; ++i) sacc[nt][i] = 0.0f;

        const uint32_t kbuf = sb + SM_K + s * 8192;
        #pragma unroll
        for (int ks = 0; ks < 4; ++ks) {
            uint32_t bv[8][2];
            #pragma unroll
            for (int nt2 = 0; nt2 < 4; ++nt2) {
                const int r  = nt2 * 16 + (lane & 7) + ((lane >> 4) << 3);
                const int cb = ks * 32 + (((lane >> 3) & 1) << 4);
                uint32_t t0, t1, t2, t3;
                ldsm_x4(t0, t1, t2, t3, kbuf + SWZ(r, cb));
                bv[nt2 * 2][0] = t0;  bv[nt2 * 2][1] = t1;
                bv[nt2 * 2 + 1][0] = t2;  bv[nt2 * 2 + 1][1] = t3;
            }
            #pragma unroll
            for (int nt = 0; nt < 8; ++nt)
                mma16816(sacc[nt], qf[ks], bv[nt]);
        }

        // ---- online softmax (base-2) ----
        #pragma unroll
        for (int hf = 0; hf < 2; ++hf) {
            float tmax = -1e30f;
            #pragma unroll
            for (int nt = 0; nt < 8; ++nt)
                tmax = fmaxf(tmax, fmaxf(sacc[nt][2 * hf], sacc[nt][2 * hf + 1]));
            tmax = fmaxf(tmax, __shfl_xor_sync(0xffffffffu, tmax, 1));
            tmax = fmaxf(tmax, __shfl_xor_sync(0xffffffffu, tmax, 2));

            const float mn    = fmaxf(m2[hf], tmax);
            const float alpha = exp2f(m2[hf] - mn);
            m2[hf] = mn;

            float rs = 0.0f;
            #pragma unroll
            for (int nt = 0; nt < 8; ++nt) {
                const float p0 = exp2f(sacc[nt][2 * hf]     - mn);
                const float p1 = exp2f(sacc[nt][2 * hf + 1] - mn);
                sacc[nt][2 * hf] = p0;  sacc[nt][2 * hf + 1] = p1;
                rs += p0 + p1;
            }
            rs += __shfl_xor_sync(0xffffffffu, rs, 1);
            rs += __shfl_xor_sync(0xffffffffu, rs, 2);
            l2[hf] = l2[hf] * alpha + rs;

            #pragma unroll
            for (int nt = 0; nt < 8; ++nt) {
                oacc[nt][2 * hf]     *= alpha;
                oacc[nt][2 * hf + 1] *= alpha;
            }
        }

        // ---- P fragments (registers only) ----
        uint32_t pf[4][4];
        #pragma unroll
        for (int c = 0; c < 4; ++c) {
            pf[c][0] = packh2(sacc[2 * c][0],     sacc[2 * c][1]);
            pf[c][1] = packh2(sacc[2 * c][2],     sacc[2 * c][3]);
            pf[c][2] = packh2(sacc[2 * c + 1][0], sacc[2 * c + 1][1]);
            pf[c][3] = packh2(sacc[2 * c + 1][2], sacc[2 * c + 1][3]);
        }

        // ---- O += P V ----
        const uint32_t vbuf = sb + SM_V + s * 8192;
        #pragma unroll
        for (int ks = 0; ks < 4; ++ks) {
            uint32_t vv[8][2];
            #pragma unroll
            for (int ng = 0; ng < 4; ++ng) {
                const int r  = ks * 16 + (lane & 15);
                const int cb = ng * 32 + ((lane >> 4) << 4);
                uint32_t t0, t1, t2, t3;
                ldsm_x4_t(t0, t1, t2, t3, vbuf + SWZ(r, cb));
                vv[ng * 2][0] = t0;  vv[ng * 2][1] = t1;
                vv[ng * 2 + 1][0] = t2;  vv[ng * 2 + 1][1] = t3;
            }
            #pragma unroll
            for (int nt = 0; nt < 8; ++nt)
                mma16816(oacc[nt], pf[ks], vv[nt]);
        }

        if (t + 2 < AIT) load_kv(t + 2, ls);
        cp_commit();
        s  = (s  == 2) ? 0 : s + 1;
        ls = (ls == 2) ? 0 : ls + 1;
    }

    // ---- epilogue: normalize, write fp16 A rows [M,1024] at col h*64+d ----
    const int g  = lane >> 2;
    const int tg = lane & 3;
    const float inv0 = __fdividef(1.0f, l2[0]);
    const float inv1 = __fdividef(1.0f, l2[1]);
    const int row0 = b * S_SEQ + qt * AQ + w * 16 + g;
    #pragma unroll
    for (int nt = 0; nt < 8; ++nt) {
        const int col = h * HD + nt * 8 + tg * 2;
        *(uint32_t*)(Aout + (size_t)row0 * D_MODEL + col) =
            packh2(oacc[nt][0] * inv0, oacc[nt][1] * inv0);
        *(uint32_t*)(Aout + (size_t)(row0 + 8) * D_MODEL + col) =
            packh2(oacc[nt][2] * inv1, oacc[nt][3] * inv1);
    }
}

// ---------------------------------------------------------------------------
// Launch
// ---------------------------------------------------------------------------
extern "C" void kernel_launch(void* const* d_in, const int* in_sizes, int n_in,
                              void* d_out, int out_size)
{
    const float* x     = (const float*)d_in[0];
    const float* W_qkv = (const float*)d_in[1];
    const float* b_qkv = (const float*)d_in[2];
    const float* W_out = (const float*)d_in[3];
    const float* b_out = (const float*)d_in[4];
    float* out = (float*)d_out;

    __half *Ah, *Bqkv, *Bout, *qkvh;
    cudaGetSymbolAddress((void**)&Ah,   g_Ah);
    cudaGetSymbolAddress((void**)&Bqkv, g_Bqkv);
    cudaGetSymbolAddress((void**)&Bout, g_Bout);
    cudaGetSymbolAddress((void**)&qkvh, g_qkvh);

    cudaFuncSetAttribute(gemm_h_mma<0>,
                         cudaFuncAttributeMaxDynamicSharedMemorySize, GEMM_SMEM);
    cudaFuncSetAttribute(gemm_h_mma<1>,
                         cudaFuncAttributeMaxDynamicSharedMemorySize, GEMM_SMEM);
    cudaFuncSetAttribute(flash_attn_h,
                         cudaFuncAttributeMaxDynamicSharedMemorySize, ATT_SMEM);

    // 1) fused prep: x -> fp16, both weights -> transposed fp16
    prep_kernel<<<PREP_XB + PREP_QB + PREP_OB, 256>>>(x, W_qkv, W_out, Ah, Bqkv, Bout);

    // 2) QKV projection (HMMA fp16) -> fp16 q|k|v [B,H,S,64], q pre-scaled
    gemm_h_mma<1><<<dim3(QKV_N / BN, M_ROWS / BM), 256, GEMM_SMEM>>>(
        Ah, Bqkv, b_qkv, nullptr, qkvh, QKV_N);

    // 3) Flash attention (HMMA fp16, base-2 softmax) -> fp16 A
    flash_attn_h<<<dim3(S_SEQ / AQ, H_HEADS, B_BATCH), 256, ATT_SMEM>>>(qkvh, Ah);

    // 4) Output projection (HMMA fp16) -> out
    gemm_h_mma<0><<<dim3(D_MODEL / BN, M_ROWS / BM), 256, GEMM_SMEM>>>(
        Ah, Bout, b_out, out, nullptr, D_MODEL);
}